// round 1
// baseline (speedup 1.0000x reference)
#include <cuda_runtime.h>
#include <cstdint>
#include <cstddef>

#define B_   64
#define T_   512
#define H_   256
#define G3_  768
#define M_   (B_*T_)

#define RG     128    // recurrence CTAs (all resident: 128 <= 148 SMs)
#define RU     2      // hidden units per recurrence CTA (RG*RU == H_)
#define RT_    256    // recurrence threads (64 b x 2 u x 2 k-halves)
#define HPITCH 260    // smem pitch for h tile (conflict-free LDS.128, lane=b)

// ---------------- static device scratch (no runtime allocation) ----------------
__device__ float g_xg[(size_t)T_ * G3_ * B_];   // [t][gate_row 0..767][b]  96 MB
__device__ float g_seqA[(size_t)M_ * H_];       // [b][t][h]                32 MB
__device__ float g_seqB[(size_t)M_ * H_];       // [b][t][h]                32 MB
__device__ float g_h[2][B_ * H_];               // double-buffered hidden state
__device__ int   g_bar[3 * T_];                 // per-step barrier counters

// ---------------- zero barrier counters + hidden state ----------------
__global__ void zero_kernel() {
    int i = blockIdx.x * blockDim.x + threadIdx.x;
    if (i < 3 * T_) g_bar[i] = 0;
    if (i < 2 * B_ * H_) ((float*)g_h)[i] = 0.0f;
}

// ---------------- input projection GEMM: xg = A @ W^T + bias ----------------
// A: [M_][K] row-major (rows are m = b*T + t), W: [768][K], out -> g_xg[t][n][b]
__global__ __launch_bounds__(256, 2)
void proj_gemm_kernel(const float* __restrict__ xext,
                      const float* __restrict__ W,
                      const float* __restrict__ bias,
                      int K, int asel)
{
    const float* A = (asel == 0) ? xext : (asel == 1 ? g_seqA : g_seqB);
    __shared__ float As[2][8][128];
    __shared__ float Ws[2][8][128];
    const int t  = threadIdx.x;
    const int bm = blockIdx.x;          // M tile (256 tiles)
    const int bn = blockIdx.y;          // N tile (6 tiles)
    const int lr = t >> 1;              // load row 0..127
    const int lc = (t & 1) << 2;        // 0 or 4
    const float* Ag = A + (size_t)(bm * 128 + lr) * K + lc;
    const float* Wg = W + (size_t)(bn * 128 + lr) * K + lc;

    float4 av = *(const float4*)Ag;
    float4 wv = *(const float4*)Wg;
    As[0][lc + 0][lr] = av.x; As[0][lc + 1][lr] = av.y;
    As[0][lc + 2][lr] = av.z; As[0][lc + 3][lr] = av.w;
    Ws[0][lc + 0][lr] = wv.x; Ws[0][lc + 1][lr] = wv.y;
    Ws[0][lc + 2][lr] = wv.z; Ws[0][lc + 3][lr] = wv.w;
    __syncthreads();

    float acc[8][8];
#pragma unroll
    for (int i = 0; i < 8; i++)
#pragma unroll
        for (int j = 0; j < 8; j++) acc[i][j] = 0.0f;

    const int tx = (t & 15) << 3;       // N offset within tile
    const int ty = (t >> 4) << 3;       // M offset within tile
    const int nk = K >> 3;
    for (int kt = 0; kt < nk; ++kt) {
        const int cur = kt & 1;
        float4 av2, wv2;
        if (kt + 1 < nk) {
            av2 = *(const float4*)(Ag + (size_t)(kt + 1) * 8);
            wv2 = *(const float4*)(Wg + (size_t)(kt + 1) * 8);
        }
#pragma unroll
        for (int k = 0; k < 8; ++k) {
            float a[8], w[8];
            *(float4*)&a[0] = *(const float4*)&As[cur][k][ty];
            *(float4*)&a[4] = *(const float4*)&As[cur][k][ty + 4];
            *(float4*)&w[0] = *(const float4*)&Ws[cur][k][tx];
            *(float4*)&w[4] = *(const float4*)&Ws[cur][k][tx + 4];
#pragma unroll
            for (int i = 0; i < 8; i++)
#pragma unroll
                for (int j = 0; j < 8; j++)
                    acc[i][j] = fmaf(a[i], w[j], acc[i][j]);
        }
        if (kt + 1 < nk) {
            const int nxt = cur ^ 1;
            As[nxt][lc + 0][lr] = av2.x; As[nxt][lc + 1][lr] = av2.y;
            As[nxt][lc + 2][lr] = av2.z; As[nxt][lc + 3][lr] = av2.w;
            Ws[nxt][lc + 0][lr] = wv2.x; Ws[nxt][lc + 1][lr] = wv2.y;
            Ws[nxt][lc + 2][lr] = wv2.z; Ws[nxt][lc + 3][lr] = wv2.w;
            __syncthreads();
        }
    }

    // store with bias in [t][gate][b] layout for the serial phase
    const int n0 = bn * 128 + tx;
#pragma unroll
    for (int i = 0; i < 8; i++) {
        const int m  = bm * 128 + ty + i;
        const int bb = m >> 9;             // batch  (T_ = 512)
        const int tt = m & (T_ - 1);       // time
        float* dst = g_xg + ((size_t)tt * G3_ + n0) * B_ + bb;
#pragma unroll
        for (int j = 0; j < 8; j++)
            dst[(size_t)j * B_] = acc[i][j] + bias[n0 + j];
    }
}

// ---------------- persistent GRU recurrence for one layer ----------------
// 128 CTAs, each owns RU=2 hidden units. Per step: hg slice = h @ w_hh^T,
// gates, h update, then a global counter barrier.
__global__ __launch_bounds__(RT_, 1)
void gru_recur_kernel(const float* __restrict__ w_hh,
                      const float* __restrict__ b_hh,
                      int layer, int osel)
{
    float* out = (osel == 1) ? g_seqA : g_seqB;
    extern __shared__ float sm[];
    float* hs  = sm;                       // [64][HPITCH]
    float* ws  = sm + B_ * HPITCH;         // [3*RU][H_]
    float* red = ws + 3 * RU * H_;         // [128][3] split-K partials
    const int t   = threadIdx.x;
    const int b   = t & 63;
    const int u   = (t >> 6) & 1;          // unit within CTA
    const int kh  = t >> 7;                // K half: 0 or 1
    const int cta = blockIdx.x;
    const int j   = cta * RU + u;          // global hidden unit

    // preload this CTA's 6 rows of w_hh (rows j, H+j, 2H+j for u=0,1)
    for (int q = t; q < 3 * RU * (H_ / 4); q += RT_) {    // 384 float4s
        int row = q >> 6;                  // 0..5
        int c4  = (q & 63) << 2;
        int g   = row / RU;
        int uu  = row % RU;
        *(float4*)&ws[row * H_ + c4] =
            *(const float4*)&w_hh[((size_t)(g * H_ + cta * RU + uu)) * H_ + c4];
    }

    const float bhr = b_hh[j];
    const float bhz = b_hh[H_ + j];
    const float bhn = b_hh[2 * H_ + j];
    const float* wr = &ws[(0 * RU + u) * H_];
    const float* wz = &ws[(1 * RU + u) * H_];
    const float* wn = &ws[(2 * RU + u) * H_];
    volatile int* bar = &g_bar[layer * T_];
    __syncthreads();

    for (int step = 0; step < T_; ++step) {
        const float* hcur = g_h[step & 1];
        float*       hnxt = g_h[(step & 1) ^ 1];

        // stage full h (64x256) into smem via L2 (bypass possibly-stale L1)
#pragma unroll
        for (int q = 0; q < (B_ * H_ / 4) / RT_; ++q) {   // 16 iters
            int idx = q * RT_ + t;
            int row = idx >> 6;
            int c4  = (idx & 63) << 2;
            float4 v = __ldcg((const float4*)&hcur[row * H_ + c4]);
            *(float4*)&hs[row * HPITCH + c4] = v;
        }
        __syncthreads();

        // split-K dot: this thread does k in [kh*128, kh*128+128)
        float ar = 0.f, az = 0.f, an = 0.f;
        const float* hb = &hs[b * HPITCH];
        const int k0 = kh * (H_ / 2);
#pragma unroll 8
        for (int k = k0; k < k0 + H_ / 2; k += 4) {
            float4 h4 = *(const float4*)&hb[k];
            float4 r4 = *(const float4*)&wr[k];
            float4 z4 = *(const float4*)&wz[k];
            float4 n4 = *(const float4*)&wn[k];
            ar = fmaf(h4.x, r4.x, ar); ar = fmaf(h4.y, r4.y, ar);
            ar = fmaf(h4.z, r4.z, ar); ar = fmaf(h4.w, r4.w, ar);
            az = fmaf(h4.x, z4.x, az); az = fmaf(h4.y, z4.y, az);
            az = fmaf(h4.z, z4.z, az); az = fmaf(h4.w, z4.w, az);
            an = fmaf(h4.x, n4.x, an); an = fmaf(h4.y, n4.y, an);
            an = fmaf(h4.z, n4.z, an); an = fmaf(h4.w, n4.w, an);
        }
        if (kh) {
            red[(t & 127) * 3 + 0] = ar;
            red[(t & 127) * 3 + 1] = az;
            red[(t & 127) * 3 + 2] = an;
        }
        __syncthreads();
        if (!kh) {
            ar += red[t * 3 + 0];
            az += red[t * 3 + 1];
            an += red[t * 3 + 2];

            const float* xgp = g_xg + (size_t)step * G3_ * B_;
            float xr = xgp[(0 * H_ + j) * B_ + b];
            float xz = xgp[(1 * H_ + j) * B_ + b];
            float xn = xgp[(2 * H_ + j) * B_ + b];
            float r = 1.0f / (1.0f + expf(-(xr + ar + bhr)));
            float z = 1.0f / (1.0f + expf(-(xz + az + bhz)));
            float n = tanhf(xn + r * (an + bhn));
            float hold = hb[j];
            float hnew = (1.0f - z) * n + z * hold;
            __stcg(&hnxt[b * H_ + j], hnew);
            out[((size_t)b * T_ + step) * H_ + j] = hnew;
        }

        // global barrier: release own writes, arrive, spin, proceed
        __threadfence();
        __syncthreads();
        if (t == 0) {
            atomicAdd((int*)&bar[step], 1);
            while (bar[step] < RG) { }
        }
        __syncthreads();
    }
}

// ---------------- MLP head: relu(last @ fc1^T + b1) @ fco^T + b ----------------
__global__ void head_kernel(const float* __restrict__ fc1_w,
                            const float* __restrict__ fc1_b,
                            const float* __restrict__ fco_w,
                            const float* __restrict__ fco_b,
                            float* __restrict__ outp)
{
    const int b = blockIdx.x;
    const int f = threadIdx.x;   // 128 threads
    const float* last = &g_seqA[((size_t)b * T_ + (T_ - 1)) * H_];
    float acc = fc1_b[f];
#pragma unroll 4
    for (int k = 0; k < H_; k += 4) {
        float4 l4 = *(const float4*)&last[k];
        float4 w4 = *(const float4*)&fc1_w[(size_t)f * H_ + k];
        acc = fmaf(l4.x, w4.x, acc); acc = fmaf(l4.y, w4.y, acc);
        acc = fmaf(l4.z, w4.z, acc); acc = fmaf(l4.w, w4.w, acc);
    }
    float zz = fmaxf(acc, 0.0f) * fco_w[f];
#pragma unroll
    for (int o = 16; o > 0; o >>= 1)
        zz += __shfl_down_sync(0xffffffffu, zz, o);
    __shared__ float red4[4];
    if ((f & 31) == 0) red4[f >> 5] = zz;
    __syncthreads();
    if (f == 0) outp[b] = red4[0] + red4[1] + red4[2] + red4[3] + fco_b[0];
}

// ---------------- launch ----------------
extern "C" void kernel_launch(void* const* d_in, const int* in_sizes, int n_in,
                              void* d_out, int out_size) {
    (void)in_sizes; (void)n_in; (void)out_size;
    const float* x      = (const float*)d_in[0];
    const float* wih[3] = {(const float*)d_in[1], (const float*)d_in[5], (const float*)d_in[9]};
    const float* whh[3] = {(const float*)d_in[2], (const float*)d_in[6], (const float*)d_in[10]};
    const float* bih[3] = {(const float*)d_in[3], (const float*)d_in[7], (const float*)d_in[11]};
    const float* bhh[3] = {(const float*)d_in[4], (const float*)d_in[8], (const float*)d_in[12]};
    const float* fc1_w  = (const float*)d_in[13];
    const float* fc1_b  = (const float*)d_in[14];
    const float* fco_w  = (const float*)d_in[15];
    const float* fco_b  = (const float*)d_in[16];
    float* outp = (float*)d_out;

    const int smem = (B_ * HPITCH + 3 * RU * H_ + 128 * 3) * (int)sizeof(float);
    cudaFuncSetAttribute(gru_recur_kernel,
                         cudaFuncAttributeMaxDynamicSharedMemorySize, smem);

    dim3 pgrid(M_ / 128, G3_ / 128);
    const int Ks[3]   = {2048, H_, H_};
    const int asel[3] = {0, 1, 2};       // A source: x, seqA, seqB
    const int osel[3] = {1, 2, 1};       // out: seqA, seqB, seqA

    for (int l = 0; l < 3; ++l) {
        zero_kernel<<<128, 256>>>();
        proj_gemm_kernel<<<pgrid, 256>>>(x, wih[l], bih[l], Ks[l], asel[l]);
        gru_recur_kernel<<<RG, RT_, smem>>>(whh[l], bhh[l], l, osel[l]);
    }
    head_kernel<<<B_, 128>>>(fc1_w, fc1_b, fco_w, fco_b, outp);
}

// round 3
// speedup vs baseline: 1.1450x; 1.1450x over previous
#include <cuda_runtime.h>
#include <cuda_bf16.h>
#include <mma.h>
#include <cstdint>
#include <cstddef>

using namespace nvcuda;

#define B_   64
#define T_   512
#define H_   256
#define G3_  768
#define M_   (B_*T_)
#define K0_  2048

#define RG     128
#define RU     2
#define RT_    256
#define HPITCH 260

// GEMM smem geometry: 4 tiles (Ah, Al, Bh, Bl), each 128 rows x 64 bf16, pitch 72
#define TPITCH    72
#define TILE_ELEM (128 * TPITCH)             // 9216 elems = 18432 B
#define BUF_ELEM  (4 * TILE_ELEM)            // 36864 elems = 73728 B
#define PSMEM     (2 * BUF_ELEM * 2)         // 147456 bytes

// ---------------- static device scratch ----------------
__device__ uint16_t g_xh[(size_t)M_*K0_];
__device__ uint16_t g_xl[(size_t)M_*K0_];
__device__ uint16_t g_w0h[G3_*K0_], g_w0l[G3_*K0_];
__device__ uint16_t g_w1h[G3_*H_],  g_w1l[G3_*H_];
__device__ uint16_t g_w2h[G3_*H_],  g_w2l[G3_*H_];
__device__ uint16_t g_seqh[(size_t)M_*H_], g_seql[(size_t)M_*H_];
__device__ float    g_xg_mn[(size_t)M_*G3_];   // GEMM out [m][n] (no bias)
__device__ float    g_xg[(size_t)T_*G3_*B_];   // [t][gate][b] (+bias)
__device__ float    g_h[2][B_*H_];
__device__ int      g_bar[3*T_];

// ---------------- helpers ----------------
__device__ __forceinline__ uint32_t smem_u32(const void* p) {
    uint32_t a;
    asm("{ .reg .u64 t; cvta.to.shared.u64 t, %1; cvt.u32.u64 %0, t; }" : "=r"(a) : "l"(p));
    return a;
}
__device__ __forceinline__ void cp_async16(uint32_t dst, const void* src) {
    asm volatile("cp.async.cg.shared.global [%0], [%1], 16;" :: "r"(dst), "l"(src));
}
__device__ __forceinline__ void cp_commit() {
    asm volatile("cp.async.commit_group;");
}
template<int N>
__device__ __forceinline__ void cp_wait() {
    asm volatile("cp.async.wait_group %0;" :: "n"(N));
}

// ---------------- misc kernels ----------------
__global__ void zero_bar_kernel() {
    int i = blockIdx.x * blockDim.x + threadIdx.x;
    if (i < 3 * T_) g_bar[i] = 0;
}

// split fp32 -> (hi, lo) bf16
__global__ void split_kernel(const float* __restrict__ src, int dsel, size_t n) {
    uint16_t* hi = (dsel == 0) ? g_xh : (dsel == 1 ? g_w0h : (dsel == 2 ? g_w1h : g_w2h));
    uint16_t* lo = (dsel == 0) ? g_xl : (dsel == 1 ? g_w0l : (dsel == 2 ? g_w1l : g_w2l));
    size_t stride = (size_t)gridDim.x * blockDim.x * 4;
    for (size_t i = ((size_t)blockIdx.x * blockDim.x + threadIdx.x) * 4; i < n; i += stride) {
        float4 v = *(const float4*)(src + i);
        __nv_bfloat16 h0 = __float2bfloat16(v.x), h1 = __float2bfloat16(v.y);
        __nv_bfloat16 h2 = __float2bfloat16(v.z), h3 = __float2bfloat16(v.w);
        __nv_bfloat16 l0 = __float2bfloat16(v.x - __bfloat162float(h0));
        __nv_bfloat16 l1 = __float2bfloat16(v.y - __bfloat162float(h1));
        __nv_bfloat16 l2 = __float2bfloat16(v.z - __bfloat162float(h2));
        __nv_bfloat16 l3 = __float2bfloat16(v.w - __bfloat162float(h3));
        __nv_bfloat16* hp = (__nv_bfloat16*)(hi + i);
        __nv_bfloat16* lp = (__nv_bfloat16*)(lo + i);
        hp[0] = h0; hp[1] = h1; hp[2] = h2; hp[3] = h3;
        lp[0] = l0; lp[1] = l1; lp[2] = l2; lp[3] = l3;
    }
}

// ---------------- WMMA bf16-split projection GEMM ----------------
// C[m][n] = sum_k A[m][k]*W[n][k], A/W split (hi, lo), fp32 accum, 3 passes.
__global__ __launch_bounds__(256, 1)
void proj_wmma_kernel(int K, int asel, int wsel)
{
    extern __shared__ __nv_bfloat16 smem[];
    const uint32_t sbase = smem_u32(smem);
    const int tid = threadIdx.x;
    const int wid = tid >> 5;
    const int m0 = blockIdx.x * 128;
    const int n0 = blockIdx.y * 128;

    const uint16_t* Ah = asel ? g_seqh : g_xh;
    const uint16_t* Al = asel ? g_seql : g_xl;
    const uint16_t* Bh = (wsel == 0) ? g_w0h : (wsel == 1 ? g_w1h : g_w2h);
    const uint16_t* Bl = (wsel == 0) ? g_w0l : (wsel == 1 ? g_w1l : g_w2l);

    // zero hidden-state buffers for the recurrence that follows this launch
    if (blockIdx.x == 0 && blockIdx.y == 0) {
        float4 z = make_float4(0.f, 0.f, 0.f, 0.f);
        float4* hp = reinterpret_cast<float4*>(&g_h[0][0]);
        for (int i = tid; i < 2 * B_ * H_ / 4; i += 256) hp[i] = z;
    }

    const uint16_t* srcs[4] = {Ah + (size_t)m0 * K, Al + (size_t)m0 * K,
                               Bh + (size_t)n0 * K, Bl + (size_t)n0 * K};

    const int nC = K >> 6;   // 64-wide k chunks

    // issue chunk 0
    {
        const int k0 = 0;
#pragma unroll
        for (int i = 0; i < 16; ++i) {
            int idx  = tid + (i << 8);
            int tile = idx >> 10;
            int rem  = idx & 1023;
            int row  = rem >> 3;
            int c    = rem & 7;
            uint32_t dst = sbase + tile * (TILE_ELEM * 2) + row * (TPITCH * 2) + c * 16;
            cp_async16(dst, srcs[tile] + (size_t)row * K + k0 + c * 8);
        }
        cp_commit();
    }

    wmma::fragment<wmma::accumulator, 16, 16, 16, float> acc[2][4];
#pragma unroll
    for (int m = 0; m < 2; ++m)
#pragma unroll
        for (int n = 0; n < 4; ++n) wmma::fill_fragment(acc[m][n], 0.0f);

    const int wm = wid & 3;      // 4 m-slices of 32
    const int wn = wid >> 2;     // 2 n-slices of 64

    for (int c = 0; c < nC; ++c) {
        const int buf = c & 1;
        if (c + 1 < nC) {
            const int k0 = (c + 1) << 6;
            const uint32_t bb = sbase + ((buf ^ 1) ? BUF_ELEM * 2 : 0);
#pragma unroll
            for (int i = 0; i < 16; ++i) {
                int idx  = tid + (i << 8);
                int tile = idx >> 10;
                int rem  = idx & 1023;
                int row  = rem >> 3;
                int cc   = rem & 7;
                uint32_t dst = bb + tile * (TILE_ELEM * 2) + row * (TPITCH * 2) + cc * 16;
                cp_async16(dst, srcs[tile] + (size_t)row * K + k0 + cc * 8);
            }
            cp_commit();
            cp_wait<1>();
        } else {
            cp_wait<0>();
        }
        __syncthreads();

        const __nv_bfloat16* bufp = smem + buf * BUF_ELEM;
        const __nv_bfloat16* sAh = bufp;
        const __nv_bfloat16* sAl = bufp + TILE_ELEM;
        const __nv_bfloat16* sBh = bufp + 2 * TILE_ELEM;
        const __nv_bfloat16* sBl = bufp + 3 * TILE_ELEM;

#pragma unroll
        for (int ks = 0; ks < 4; ++ks) {
            wmma::fragment<wmma::matrix_a, 16, 16, 16, __nv_bfloat16, wmma::row_major> ah[2], al[2];
#pragma unroll
            for (int m = 0; m < 2; ++m) {
                const __nv_bfloat16* ap = sAh + (wm * 32 + m * 16) * TPITCH + ks * 16;
                wmma::load_matrix_sync(ah[m], ap, TPITCH);
                const __nv_bfloat16* alp = sAl + (wm * 32 + m * 16) * TPITCH + ks * 16;
                wmma::load_matrix_sync(al[m], alp, TPITCH);
            }
#pragma unroll
            for (int n = 0; n < 4; ++n) {
                wmma::fragment<wmma::matrix_b, 16, 16, 16, __nv_bfloat16, wmma::col_major> bh, bl;
                const __nv_bfloat16* bp = sBh + (wn * 64 + n * 16) * TPITCH + ks * 16;
                wmma::load_matrix_sync(bh, bp, TPITCH);
#pragma unroll
                for (int m = 0; m < 2; ++m) {
                    wmma::mma_sync(acc[m][n], ah[m], bh, acc[m][n]);
                    wmma::mma_sync(acc[m][n], al[m], bh, acc[m][n]);
                }
                const __nv_bfloat16* blp = sBl + (wn * 64 + n * 16) * TPITCH + ks * 16;
                wmma::load_matrix_sync(bl, blp, TPITCH);
#pragma unroll
                for (int m = 0; m < 2; ++m)
                    wmma::mma_sync(acc[m][n], ah[m], bl, acc[m][n]);
            }
        }
        __syncthreads();
    }

#pragma unroll
    for (int m = 0; m < 2; ++m)
#pragma unroll
        for (int n = 0; n < 4; ++n) {
            float* dst = g_xg_mn + (size_t)(m0 + wm * 32 + m * 16) * G3_
                                 + n0 + wn * 64 + n * 16;
            wmma::store_matrix_sync(dst, acc[m][n], G3_, wmma::mem_row_major);
        }
}

// ---------------- transpose [m][n] -> [t][gate][b], add bias ----------------
__global__ __launch_bounds__(256)
void xg_trans_kernel(const float* __restrict__ bias) {
    __shared__ float sm[64][33];
    const int t   = blockIdx.x;
    const int g0  = blockIdx.y * 32;
    const int tid = threadIdx.x;
    const int gg  = tid & 31;
    const int br  = tid >> 5;
    const float bv = bias[g0 + gg];
#pragma unroll
    for (int i = 0; i < 8; ++i) {
        int b = br + i * 8;
        sm[b][gg] = g_xg_mn[((size_t)b * T_ + t) * G3_ + g0 + gg] + bv;
    }
    __syncthreads();
    const int b  = tid & 63;
    const int gi = tid >> 6;
#pragma unroll
    for (int i = 0; i < 8; ++i) {
        int g = gi + i * 4;
        g_xg[((size_t)t * G3_ + g0 + g) * B_ + b] = sm[b][g];
    }
}

// ---------------- persistent GRU recurrence ----------------
__global__ __launch_bounds__(RT_, 1)
void gru_recur_kernel(const float* __restrict__ w_hh,
                      const float* __restrict__ b_hh,
                      int layer)
{
    extern __shared__ float smf[];
    float* hs  = smf;                      // [64][HPITCH]
    float* ws  = smf + B_ * HPITCH;        // [3*RU][H_]
    float* red = ws + 3 * RU * H_;         // [128][3]
    const int t   = threadIdx.x;
    const int b   = t & 63;
    const int u   = (t >> 6) & 1;
    const int kh  = t >> 7;
    const int cta = blockIdx.x;
    const int j   = cta * RU + u;

    for (int q = t; q < 3 * RU * (H_ / 4); q += RT_) {
        int row = q >> 6;
        int c4  = (q & 63) << 2;
        int g   = row / RU;
        int uu  = row % RU;
        *(float4*)&ws[row * H_ + c4] =
            *(const float4*)&w_hh[((size_t)(g * H_ + cta * RU + uu)) * H_ + c4];
    }

    const float bhr = b_hh[j];
    const float bhz = b_hh[H_ + j];
    const float bhn = b_hh[2 * H_ + j];
    const float* wr = &ws[(0 * RU + u) * H_];
    const float* wz = &ws[(1 * RU + u) * H_];
    const float* wn = &ws[(2 * RU + u) * H_];
    volatile int* bar = &g_bar[layer * T_];
    __nv_bfloat16* outh = (__nv_bfloat16*)g_seqh;
    __nv_bfloat16* outl = (__nv_bfloat16*)g_seql;
    __syncthreads();

    for (int step = 0; step < T_; ++step) {
        const float* hcur = g_h[step & 1];
        float*       hnxt = g_h[(step & 1) ^ 1];

#pragma unroll
        for (int q = 0; q < (B_ * H_ / 4) / RT_; ++q) {
            int idx = q * RT_ + t;
            int row = idx >> 6;
            int c4  = (idx & 63) << 2;
            float4 v = __ldcg((const float4*)&hcur[row * H_ + c4]);
            *(float4*)&hs[row * HPITCH + c4] = v;
        }
        __syncthreads();

        float ar = 0.f, az = 0.f, an = 0.f;
        const float* hb = &hs[b * HPITCH];
        const int k0 = kh * (H_ / 2);
#pragma unroll 8
        for (int k = k0; k < k0 + H_ / 2; k += 4) {
            float4 h4 = *(const float4*)&hb[k];
            float4 r4 = *(const float4*)&wr[k];
            float4 z4 = *(const float4*)&wz[k];
            float4 n4 = *(const float4*)&wn[k];
            ar = fmaf(h4.x, r4.x, ar); ar = fmaf(h4.y, r4.y, ar);
            ar = fmaf(h4.z, r4.z, ar); ar = fmaf(h4.w, r4.w, ar);
            az = fmaf(h4.x, z4.x, az); az = fmaf(h4.y, z4.y, az);
            az = fmaf(h4.z, z4.z, az); az = fmaf(h4.w, z4.w, az);
            an = fmaf(h4.x, n4.x, an); an = fmaf(h4.y, n4.y, an);
            an = fmaf(h4.z, n4.z, an); an = fmaf(h4.w, n4.w, an);
        }
        if (kh) {
            red[(t & 127) * 3 + 0] = ar;
            red[(t & 127) * 3 + 1] = az;
            red[(t & 127) * 3 + 2] = an;
        }
        __syncthreads();
        if (!kh) {
            ar += red[t * 3 + 0];
            az += red[t * 3 + 1];
            an += red[t * 3 + 2];

            const float* xgp = g_xg + (size_t)step * G3_ * B_;
            float xr = xgp[(0 * H_ + j) * B_ + b];
            float xz = xgp[(1 * H_ + j) * B_ + b];
            float xn = xgp[(2 * H_ + j) * B_ + b];
            float r = 1.0f / (1.0f + expf(-(xr + ar + bhr)));
            float z = 1.0f / (1.0f + expf(-(xz + az + bhz)));
            float n = tanhf(xn + r * (an + bhn));
            float hold = hb[j];
            float hnew = (1.0f - z) * n + z * hold;
            __stcg(&hnxt[b * H_ + j], hnew);
            __nv_bfloat16 hh = __float2bfloat16(hnew);
            __nv_bfloat16 hl = __float2bfloat16(hnew - __bfloat162float(hh));
            size_t o = ((size_t)b * T_ + step) * H_ + j;
            outh[o] = hh;
            outl[o] = hl;
        }

        __threadfence();
        __syncthreads();
        if (t == 0) {
            atomicAdd((int*)&bar[step], 1);
            while (bar[step] < RG) { __nanosleep(32); }
        }
        __syncthreads();
    }
}

// ---------------- MLP head ----------------
__global__ void head_kernel(const float* __restrict__ fc1_w,
                            const float* __restrict__ fc1_b,
                            const float* __restrict__ fco_w,
                            const float* __restrict__ fco_b,
                            float* __restrict__ outp)
{
    const int b = blockIdx.x;
    const int f = threadIdx.x;
    const float* last = &g_h[0][b * H_];
    float acc = fc1_b[f];
#pragma unroll 4
    for (int k = 0; k < H_; k += 4) {
        float4 l4 = *(const float4*)&last[k];
        float4 w4 = *(const float4*)&fc1_w[(size_t)f * H_ + k];
        acc = fmaf(l4.x, w4.x, acc); acc = fmaf(l4.y, w4.y, acc);
        acc = fmaf(l4.z, w4.z, acc); acc = fmaf(l4.w, w4.w, acc);
    }
    float zz = fmaxf(acc, 0.0f) * fco_w[f];
#pragma unroll
    for (int o = 16; o > 0; o >>= 1)
        zz += __shfl_down_sync(0xffffffffu, zz, o);
    __shared__ float red4[4];
    if ((f & 31) == 0) red4[f >> 5] = zz;
    __syncthreads();
    if (f == 0) outp[b] = red4[0] + red4[1] + red4[2] + red4[3] + fco_b[0];
}

// ---------------- launch ----------------
extern "C" void kernel_launch(void* const* d_in, const int* in_sizes, int n_in,
                              void* d_out, int out_size) {
    (void)in_sizes; (void)n_in; (void)out_size;
    const float* x      = (const float*)d_in[0];
    const float* wih[3] = {(const float*)d_in[1], (const float*)d_in[5], (const float*)d_in[9]};
    const float* whh[3] = {(const float*)d_in[2], (const float*)d_in[6], (const float*)d_in[10]};
    const float* bih[3] = {(const float*)d_in[3], (const float*)d_in[7], (const float*)d_in[11]};
    const float* bhh[3] = {(const float*)d_in[4], (const float*)d_in[8], (const float*)d_in[12]};
    const float* fc1_w  = (const float*)d_in[13];
    const float* fc1_b  = (const float*)d_in[14];
    const float* fco_w  = (const float*)d_in[15];
    const float* fco_b  = (const float*)d_in[16];
    float* outp = (float*)d_out;

    cudaFuncSetAttribute(proj_wmma_kernel,
                         cudaFuncAttributeMaxDynamicSharedMemorySize, PSMEM);
    const int rsmem = (B_ * HPITCH + 3 * RU * H_ + 128 * 3) * (int)sizeof(float);
    cudaFuncSetAttribute(gru_recur_kernel,
                         cudaFuncAttributeMaxDynamicSharedMemorySize, rsmem);

    zero_bar_kernel<<<6, 256>>>();
    split_kernel<<<2048, 256>>>(x,      0, (size_t)M_ * K0_);
    split_kernel<<<256,  256>>>(wih[0], 1, (size_t)G3_ * K0_);
    split_kernel<<<64,   256>>>(wih[1], 2, (size_t)G3_ * H_);
    split_kernel<<<64,   256>>>(wih[2], 3, (size_t)G3_ * H_);

    dim3 pgrid(M_ / 128, G3_ / 128);
    dim3 tgrid(T_, G3_ / 32);
    const int Ks[3]   = {K0_, H_, H_};
    const int asel[3] = {0, 1, 1};

    for (int l = 0; l < 3; ++l) {
        proj_wmma_kernel<<<pgrid, 256, PSMEM>>>(Ks[l], asel[l], l);
        xg_trans_kernel<<<tgrid, 256>>>(bih[l]);
        gru_recur_kernel<<<RG, RT_, rsmem>>>(whh[l], bhh[l], l);
    }
    head_kernel<<<B_, 128>>>(fc1_w, fc1_b, fco_w, fco_b, outp);
}

// round 4
// speedup vs baseline: 1.2378x; 1.0810x over previous
#include <cuda_runtime.h>
#include <cuda_bf16.h>
#include <mma.h>
#include <cstdint>
#include <cstddef>

using namespace nvcuda;

#define B_   64
#define T_   512
#define H_   256
#define G3_  768
#define M_   (B_*T_)
#define K0_  2048

#define RG     128
#define RU     2
#define RT_    256
#define HPITCH 260

// GEMM smem geometry: 4 tiles (Ah, Al, Bh, Bl), each 128 rows x 64 bf16, pitch 72
#define TPITCH    72
#define TILE_ELEM (128 * TPITCH)
#define BUF_ELEM  (4 * TILE_ELEM)
#define PSMEM     (2 * BUF_ELEM * 2)

// ---------------- static device scratch ----------------
__device__ uint16_t g_xh[(size_t)M_*K0_];
__device__ uint16_t g_xl[(size_t)M_*K0_];
__device__ uint16_t g_w0h[G3_*K0_], g_w0l[G3_*K0_];
__device__ uint16_t g_w1h[G3_*H_],  g_w1l[G3_*H_];
__device__ uint16_t g_w2h[G3_*H_],  g_w2l[G3_*H_];
__device__ uint16_t g_seqh[(size_t)M_*H_], g_seql[(size_t)M_*H_];
__device__ float    g_xg_mn[(size_t)M_*G3_];
__device__ float    g_xg[(size_t)T_*G3_*B_];
__device__ float    g_h[2][B_*H_];
__device__ int      g_leaf[3*T_*8];     // two-level barrier: 8 leaves x 16 CTAs
__device__ int      g_root[3*T_];

// ---------------- helpers ----------------
__device__ __forceinline__ uint32_t smem_u32(const void* p) {
    uint32_t a;
    asm("{ .reg .u64 t; cvta.to.shared.u64 t, %1; cvt.u32.u64 %0, t; }" : "=r"(a) : "l"(p));
    return a;
}
__device__ __forceinline__ void cp_async16(uint32_t dst, const void* src) {
    asm volatile("cp.async.cg.shared.global [%0], [%1], 16;" :: "r"(dst), "l"(src));
}
__device__ __forceinline__ void cp_commit() {
    asm volatile("cp.async.commit_group;");
}
template<int N>
__device__ __forceinline__ void cp_wait() {
    asm volatile("cp.async.wait_group %0;" :: "n"(N));
}

// ---------------- zero barrier counters ----------------
__global__ void zero_bar_kernel() {
    int i = blockIdx.x * blockDim.x + threadIdx.x;
    if (i < 3 * T_ * 8) g_leaf[i] = 0;
    if (i < 3 * T_)     g_root[i] = 0;
}

// ---------------- splits ----------------
__global__ void split_x_kernel(const float* __restrict__ src) {
    const size_t n = (size_t)M_ * K0_;
    size_t stride = (size_t)gridDim.x * blockDim.x * 4;
    for (size_t i = ((size_t)blockIdx.x * blockDim.x + threadIdx.x) * 4; i < n; i += stride) {
        float4 v = *(const float4*)(src + i);
        __nv_bfloat16 h0 = __float2bfloat16(v.x), h1 = __float2bfloat16(v.y);
        __nv_bfloat16 h2 = __float2bfloat16(v.z), h3 = __float2bfloat16(v.w);
        __nv_bfloat16* hp = (__nv_bfloat16*)(g_xh + i);
        __nv_bfloat16* lp = (__nv_bfloat16*)(g_xl + i);
        hp[0] = h0; hp[1] = h1; hp[2] = h2; hp[3] = h3;
        lp[0] = __float2bfloat16(v.x - __bfloat162float(h0));
        lp[1] = __float2bfloat16(v.y - __bfloat162float(h1));
        lp[2] = __float2bfloat16(v.z - __bfloat162float(h2));
        lp[3] = __float2bfloat16(v.w - __bfloat162float(h3));
    }
}

__global__ void split_w_kernel(const float* __restrict__ s0,
                               const float* __restrict__ s1,
                               const float* __restrict__ s2) {
    const int a = blockIdx.y;
    const float* src = (a == 0) ? s0 : (a == 1 ? s1 : s2);
    uint16_t* hi = (a == 0) ? g_w0h : (a == 1 ? g_w1h : g_w2h);
    uint16_t* lo = (a == 0) ? g_w0l : (a == 1 ? g_w1l : g_w2l);
    const size_t n = (a == 0) ? (size_t)G3_ * K0_ : (size_t)G3_ * H_;
    size_t stride = (size_t)gridDim.x * blockDim.x * 4;
    for (size_t i = ((size_t)blockIdx.x * blockDim.x + threadIdx.x) * 4; i < n; i += stride) {
        float4 v = *(const float4*)(src + i);
        __nv_bfloat16 h0 = __float2bfloat16(v.x), h1 = __float2bfloat16(v.y);
        __nv_bfloat16 h2 = __float2bfloat16(v.z), h3 = __float2bfloat16(v.w);
        __nv_bfloat16* hp = (__nv_bfloat16*)(hi + i);
        __nv_bfloat16* lp = (__nv_bfloat16*)(lo + i);
        hp[0] = h0; hp[1] = h1; hp[2] = h2; hp[3] = h3;
        lp[0] = __float2bfloat16(v.x - __bfloat162float(h0));
        lp[1] = __float2bfloat16(v.y - __bfloat162float(h1));
        lp[2] = __float2bfloat16(v.z - __bfloat162float(h2));
        lp[3] = __float2bfloat16(v.w - __bfloat162float(h3));
    }
}

// ---------------- WMMA bf16-split projection GEMM ----------------
__global__ __launch_bounds__(256, 1)
void proj_wmma_kernel(int K, int asel, int wsel)
{
    extern __shared__ __nv_bfloat16 smem[];
    const uint32_t sbase = smem_u32(smem);
    const int tid = threadIdx.x;
    const int wid = tid >> 5;
    const int m0 = blockIdx.x * 128;
    const int n0 = blockIdx.y * 128;

    const uint16_t* Ah = asel ? g_seqh : g_xh;
    const uint16_t* Al = asel ? g_seql : g_xl;
    const uint16_t* Bh = (wsel == 0) ? g_w0h : (wsel == 1 ? g_w1h : g_w2h);
    const uint16_t* Bl = (wsel == 0) ? g_w0l : (wsel == 1 ? g_w1l : g_w2l);

    // zero hidden-state buffers for the recurrence that follows this launch
    if (blockIdx.x == 0 && blockIdx.y == 0) {
        float4 z = make_float4(0.f, 0.f, 0.f, 0.f);
        float4* hp = reinterpret_cast<float4*>(&g_h[0][0]);
        for (int i = tid; i < 2 * B_ * H_ / 4; i += 256) hp[i] = z;
    }

    const uint16_t* srcs[4] = {Ah + (size_t)m0 * K, Al + (size_t)m0 * K,
                               Bh + (size_t)n0 * K, Bl + (size_t)n0 * K};

    const int nC = K >> 6;

    {
#pragma unroll
        for (int i = 0; i < 16; ++i) {
            int idx  = tid + (i << 8);
            int tile = idx >> 10;
            int rem  = idx & 1023;
            int row  = rem >> 3;
            int c    = rem & 7;
            uint32_t dst = sbase + tile * (TILE_ELEM * 2) + row * (TPITCH * 2) + c * 16;
            cp_async16(dst, srcs[tile] + (size_t)row * K + c * 8);
        }
        cp_commit();
    }

    wmma::fragment<wmma::accumulator, 16, 16, 16, float> acc[2][4];
#pragma unroll
    for (int m = 0; m < 2; ++m)
#pragma unroll
        for (int n = 0; n < 4; ++n) wmma::fill_fragment(acc[m][n], 0.0f);

    const int wm = wid & 3;
    const int wn = wid >> 2;

    for (int c = 0; c < nC; ++c) {
        const int buf = c & 1;
        if (c + 1 < nC) {
            const int k0 = (c + 1) << 6;
            const uint32_t bb = sbase + ((buf ^ 1) ? BUF_ELEM * 2 : 0);
#pragma unroll
            for (int i = 0; i < 16; ++i) {
                int idx  = tid + (i << 8);
                int tile = idx >> 10;
                int rem  = idx & 1023;
                int row  = rem >> 3;
                int cc   = rem & 7;
                uint32_t dst = bb + tile * (TILE_ELEM * 2) + row * (TPITCH * 2) + cc * 16;
                cp_async16(dst, srcs[tile] + (size_t)row * K + k0 + cc * 8);
            }
            cp_commit();
            cp_wait<1>();
        } else {
            cp_wait<0>();
        }
        __syncthreads();

        const __nv_bfloat16* bufp = smem + buf * BUF_ELEM;
        const __nv_bfloat16* sAh = bufp;
        const __nv_bfloat16* sAl = bufp + TILE_ELEM;
        const __nv_bfloat16* sBh = bufp + 2 * TILE_ELEM;
        const __nv_bfloat16* sBl = bufp + 3 * TILE_ELEM;

#pragma unroll
        for (int ks = 0; ks < 4; ++ks) {
            wmma::fragment<wmma::matrix_a, 16, 16, 16, __nv_bfloat16, wmma::row_major> ah[2], al[2];
#pragma unroll
            for (int m = 0; m < 2; ++m) {
                wmma::load_matrix_sync(ah[m], sAh + (wm * 32 + m * 16) * TPITCH + ks * 16, TPITCH);
                wmma::load_matrix_sync(al[m], sAl + (wm * 32 + m * 16) * TPITCH + ks * 16, TPITCH);
            }
#pragma unroll
            for (int n = 0; n < 4; ++n) {
                wmma::fragment<wmma::matrix_b, 16, 16, 16, __nv_bfloat16, wmma::col_major> bh, bl;
                wmma::load_matrix_sync(bh, sBh + (wn * 64 + n * 16) * TPITCH + ks * 16, TPITCH);
#pragma unroll
                for (int m = 0; m < 2; ++m) {
                    wmma::mma_sync(acc[m][n], ah[m], bh, acc[m][n]);
                    wmma::mma_sync(acc[m][n], al[m], bh, acc[m][n]);
                }
                wmma::load_matrix_sync(bl, sBl + (wn * 64 + n * 16) * TPITCH + ks * 16, TPITCH);
#pragma unroll
                for (int m = 0; m < 2; ++m)
                    wmma::mma_sync(acc[m][n], ah[m], bl, acc[m][n]);
            }
        }
        __syncthreads();
    }

#pragma unroll
    for (int m = 0; m < 2; ++m)
#pragma unroll
        for (int n = 0; n < 4; ++n) {
            float* dst = g_xg_mn + (size_t)(m0 + wm * 32 + m * 16) * G3_
                                 + n0 + wn * 64 + n * 16;
            wmma::store_matrix_sync(dst, acc[m][n], G3_, wmma::mem_row_major);
        }
}

// ---------------- transpose [m][n] -> [t][gate][b], add bias ----------------
__global__ __launch_bounds__(256)
void xg_trans_kernel(const float* __restrict__ bias) {
    __shared__ float sm[64][33];
    const int t   = blockIdx.x;
    const int g0  = blockIdx.y * 32;
    const int tid = threadIdx.x;
    const int gg  = tid & 31;
    const int br  = tid >> 5;
    const float bv = bias[g0 + gg];
#pragma unroll
    for (int i = 0; i < 8; ++i) {
        int b = br + i * 8;
        sm[b][gg] = g_xg_mn[((size_t)b * T_ + t) * G3_ + g0 + gg] + bv;
    }
    __syncthreads();
    const int b  = tid & 63;
    const int gi = tid >> 6;
#pragma unroll
    for (int i = 0; i < 8; ++i) {
        int g = gi + i * 4;
        g_xg[((size_t)t * G3_ + g0 + g) * B_ + b] = sm[b][g];
    }
}

// ---------------- persistent GRU recurrence ----------------
__global__ __launch_bounds__(RT_, 1)
void gru_recur_kernel(const float* __restrict__ w_hh,
                      const float* __restrict__ b_hh,
                      int layer)
{
    extern __shared__ float smf[];
    float* hs  = smf;                      // [64][HPITCH]
    float* ws  = smf + B_ * HPITCH;        // [3*RU][H_]
    float* red = ws + 3 * RU * H_;         // [128][3]
    const int t   = threadIdx.x;
    const int b   = t & 63;
    const int u   = (t >> 6) & 1;
    const int kh  = t >> 7;
    const int cta = blockIdx.x;
    const int j   = cta * RU + u;

    for (int q = t; q < 3 * RU * (H_ / 4); q += RT_) {
        int row = q >> 6;
        int c4  = (q & 63) << 2;
        int g   = row / RU;
        int uu  = row % RU;
        *(float4*)&ws[row * H_ + c4] =
            *(const float4*)&w_hh[((size_t)(g * H_ + cta * RU + uu)) * H_ + c4];
    }

    const float bhr = b_hh[j];
    const float bhz = b_hh[H_ + j];
    const float bhn = b_hh[2 * H_ + j];
    const float* wr = &ws[(0 * RU + u) * H_];
    const float* wz = &ws[(1 * RU + u) * H_];
    const float* wn = &ws[(2 * RU + u) * H_];
    __nv_bfloat16* outh = (__nv_bfloat16*)g_seqh;
    __nv_bfloat16* outl = (__nv_bfloat16*)g_seql;
    __syncthreads();

    for (int step = 0; step < T_; ++step) {
        const float* hcur = g_h[step & 1];
        float*       hnxt = g_h[(step & 1) ^ 1];

        // prefetch precomputed xg for this step (independent of barrier/h)
        float xr = 0.f, xz = 0.f, xn = 0.f;
        if (!kh) {
            const float* xgp = g_xg + (size_t)step * G3_ * B_;
            xr = __ldg(&xgp[(0 * H_ + j) * B_ + b]);
            xz = __ldg(&xgp[(1 * H_ + j) * B_ + b]);
            xn = __ldg(&xgp[(2 * H_ + j) * B_ + b]);
        }

#pragma unroll
        for (int q = 0; q < (B_ * H_ / 4) / RT_; ++q) {
            int idx = q * RT_ + t;
            int row = idx >> 6;
            int c4  = (idx & 63) << 2;
            float4 v = __ldcg((const float4*)&hcur[row * H_ + c4]);
            *(float4*)&hs[row * HPITCH + c4] = v;
        }
        __syncthreads();

        float ar = 0.f, az = 0.f, an = 0.f;
        const float* hb = &hs[b * HPITCH];
        const int k0 = kh * (H_ / 2);
#pragma unroll 8
        for (int k = k0; k < k0 + H_ / 2; k += 4) {
            float4 h4 = *(const float4*)&hb[k];
            float4 r4 = *(const float4*)&wr[k];
            float4 z4 = *(const float4*)&wz[k];
            float4 n4 = *(const float4*)&wn[k];
            ar = fmaf(h4.x, r4.x, ar); ar = fmaf(h4.y, r4.y, ar);
            ar = fmaf(h4.z, r4.z, ar); ar = fmaf(h4.w, r4.w, ar);
            az = fmaf(h4.x, z4.x, az); az = fmaf(h4.y, z4.y, az);
            az = fmaf(h4.z, z4.z, az); az = fmaf(h4.w, z4.w, az);
            an = fmaf(h4.x, n4.x, an); an = fmaf(h4.y, n4.y, an);
            an = fmaf(h4.z, n4.z, an); an = fmaf(h4.w, n4.w, an);
        }
        if (kh) {
            red[(t & 127) * 3 + 0] = ar;
            red[(t & 127) * 3 + 1] = az;
            red[(t & 127) * 3 + 2] = an;
        }
        __syncthreads();
        if (!kh) {
            ar += red[t * 3 + 0];
            az += red[t * 3 + 1];
            an += red[t * 3 + 2];

            float r = 1.0f / (1.0f + __expf(-(xr + ar + bhr)));
            float z = 1.0f / (1.0f + __expf(-(xz + az + bhz)));
            float n = tanhf(xn + r * (an + bhn));
            float hold = hb[j];
            float hnew = (1.0f - z) * n + z * hold;
            __stcg(&hnxt[b * H_ + j], hnew);
            __nv_bfloat16 hh = __float2bfloat16(hnew);
            __nv_bfloat16 hl = __float2bfloat16(hnew - __bfloat162float(hh));
            size_t o = ((size_t)b * T_ + step) * H_ + j;
            outh[o] = hh;
            outl[o] = hl;
        }

        if (step + 1 < T_) {
            // two-level barrier: 8 leaves x 16 CTAs, then root
            __threadfence();
            __syncthreads();
            if (t == 0) {
                const int sidx = layer * T_ + step;
                int v = atomicAdd(&g_leaf[sidx * 8 + (cta & 7)], 1);
                if (v == 15) atomicAdd(&g_root[sidx], 1);
                volatile int* rp = &g_root[sidx];
                while (*rp < 8) { }
            }
            __syncthreads();
        }
    }
}

// ---------------- MLP head ----------------
__global__ void head_kernel(const float* __restrict__ fc1_w,
                            const float* __restrict__ fc1_b,
                            const float* __restrict__ fco_w,
                            const float* __restrict__ fco_b,
                            float* __restrict__ outp)
{
    const int b = blockIdx.x;
    const int f = threadIdx.x;
    const float* last = &g_h[0][b * H_];
    float acc = fc1_b[f];
#pragma unroll 4
    for (int k = 0; k < H_; k += 4) {
        float4 l4 = *(const float4*)&last[k];
        float4 w4 = *(const float4*)&fc1_w[(size_t)f * H_ + k];
        acc = fmaf(l4.x, w4.x, acc); acc = fmaf(l4.y, w4.y, acc);
        acc = fmaf(l4.z, w4.z, acc); acc = fmaf(l4.w, w4.w, acc);
    }
    float zz = fmaxf(acc, 0.0f) * fco_w[f];
#pragma unroll
    for (int o = 16; o > 0; o >>= 1)
        zz += __shfl_down_sync(0xffffffffu, zz, o);
    __shared__ float red4[4];
    if ((f & 31) == 0) red4[f >> 5] = zz;
    __syncthreads();
    if (f == 0) outp[b] = red4[0] + red4[1] + red4[2] + red4[3] + fco_b[0];
}

// ---------------- launch ----------------
extern "C" void kernel_launch(void* const* d_in, const int* in_sizes, int n_in,
                              void* d_out, int out_size) {
    (void)in_sizes; (void)n_in; (void)out_size;
    const float* x      = (const float*)d_in[0];
    const float* wih[3] = {(const float*)d_in[1], (const float*)d_in[5], (const float*)d_in[9]};
    const float* whh[3] = {(const float*)d_in[2], (const float*)d_in[6], (const float*)d_in[10]};
    const float* bih[3] = {(const float*)d_in[3], (const float*)d_in[7], (const float*)d_in[11]};
    const float* bhh[3] = {(const float*)d_in[4], (const float*)d_in[8], (const float*)d_in[12]};
    const float* fc1_w  = (const float*)d_in[13];
    const float* fc1_b  = (const float*)d_in[14];
    const float* fco_w  = (const float*)d_in[15];
    const float* fco_b  = (const float*)d_in[16];
    float* outp = (float*)d_out;

    cudaFuncSetAttribute(proj_wmma_kernel,
                         cudaFuncAttributeMaxDynamicSharedMemorySize, PSMEM);
    const int rsmem = (B_ * HPITCH + 3 * RU * H_ + 128 * 3) * (int)sizeof(float);
    cudaFuncSetAttribute(gru_recur_kernel,
                         cudaFuncAttributeMaxDynamicSharedMemorySize, rsmem);

    zero_bar_kernel<<<48, 256>>>();                         // 1
    split_x_kernel<<<2048, 256>>>(x);                       // 2
    split_w_kernel<<<dim3(256, 3), 256>>>(wih[0], wih[1], wih[2]);  // 3

    dim3 pgrid(M_ / 128, G3_ / 128);
    dim3 tgrid(T_, G3_ / 32);
    const int Ks[3]   = {K0_, H_, H_};
    const int asel[3] = {0, 1, 1};

    for (int l = 0; l < 3; ++l) {
        proj_wmma_kernel<<<pgrid, 256, PSMEM>>>(Ks[l], asel[l], l);   // 4
        xg_trans_kernel<<<tgrid, 256>>>(bih[l]);                      // 5
        gru_recur_kernel<<<RG, RT_, rsmem>>>(whh[l], bhh[l], l);      // 6 <- ncu target
    }
    head_kernel<<<B_, 128>>>(fc1_w, fc1_b, fco_w, fco_b, outp);
}

// round 5
// speedup vs baseline: 1.6468x; 1.3304x over previous
#include <cuda_runtime.h>
#include <cuda_bf16.h>
#include <mma.h>
#include <cstdint>
#include <cstddef>

using namespace nvcuda;

#define B_   64
#define T_   512
#define H_   256
#define G3_  768
#define M_   (B_*T_)
#define K0_  2048

// recurrence decomposition: 16 batch-groups x 8 unit-groups = 128 CTAs
#define GB_  16
#define GU_  8
#define BC_  4     // batches per CTA
#define UC_  32    // units per CTA
#define RT_  256   // threads (128 (b,u) pairs x 2 k-halves)
#define WPITCH 260

// GEMM smem geometry
#define TPITCH    72
#define TILE_ELEM (128 * TPITCH)
#define BUF_ELEM  (4 * TILE_ELEM)
#define PSMEM     (2 * BUF_ELEM * 2)

#define RSMEM ((3*UC_*WPITCH + BC_*WPITCH + 128*3) * (int)sizeof(float))

// ---------------- static device scratch ----------------
__device__ uint16_t g_xh[(size_t)M_*K0_];
__device__ uint16_t g_xl[(size_t)M_*K0_];
__device__ uint16_t g_w0h[G3_*K0_], g_w0l[G3_*K0_];
__device__ uint16_t g_w1h[G3_*H_],  g_w1l[G3_*H_];
__device__ uint16_t g_w2h[G3_*H_],  g_w2l[G3_*H_];
__device__ uint16_t g_seqh[(size_t)M_*H_], g_seql[(size_t)M_*H_];
__device__ float    g_xg_mn[(size_t)M_*G3_];
__device__ float    g_xg[(size_t)T_*G3_*B_];
__device__ float    g_h[2][B_*H_];
__device__ int      g_bar2[3*GB_*T_];     // per (layer, bg, step) counters

// ---------------- helpers ----------------
__device__ __forceinline__ uint32_t smem_u32(const void* p) {
    uint32_t a;
    asm("{ .reg .u64 t; cvta.to.shared.u64 t, %1; cvt.u32.u64 %0, t; }" : "=r"(a) : "l"(p));
    return a;
}
__device__ __forceinline__ void cp_async16(uint32_t dst, const void* src) {
    asm volatile("cp.async.cg.shared.global [%0], [%1], 16;" :: "r"(dst), "l"(src));
}
__device__ __forceinline__ void cp_commit() {
    asm volatile("cp.async.commit_group;");
}
template<int N>
__device__ __forceinline__ void cp_wait() {
    asm volatile("cp.async.wait_group %0;" :: "n"(N));
}

// ---------------- zero barrier counters ----------------
__global__ void zero_bar_kernel() {
    int i = blockIdx.x * blockDim.x + threadIdx.x;
    if (i < 3 * GB_ * T_) g_bar2[i] = 0;
}

// ---------------- splits ----------------
__global__ void split_x_kernel(const float* __restrict__ src) {
    const size_t n = (size_t)M_ * K0_;
    size_t stride = (size_t)gridDim.x * blockDim.x * 4;
    for (size_t i = ((size_t)blockIdx.x * blockDim.x + threadIdx.x) * 4; i < n; i += stride) {
        float4 v = *(const float4*)(src + i);
        __nv_bfloat16 h0 = __float2bfloat16(v.x), h1 = __float2bfloat16(v.y);
        __nv_bfloat16 h2 = __float2bfloat16(v.z), h3 = __float2bfloat16(v.w);
        __nv_bfloat16* hp = (__nv_bfloat16*)(g_xh + i);
        __nv_bfloat16* lp = (__nv_bfloat16*)(g_xl + i);
        hp[0] = h0; hp[1] = h1; hp[2] = h2; hp[3] = h3;
        lp[0] = __float2bfloat16(v.x - __bfloat162float(h0));
        lp[1] = __float2bfloat16(v.y - __bfloat162float(h1));
        lp[2] = __float2bfloat16(v.z - __bfloat162float(h2));
        lp[3] = __float2bfloat16(v.w - __bfloat162float(h3));
    }
}

__global__ void split_w_kernel(const float* __restrict__ s0,
                               const float* __restrict__ s1,
                               const float* __restrict__ s2) {
    const int a = blockIdx.y;
    const float* src = (a == 0) ? s0 : (a == 1 ? s1 : s2);
    uint16_t* hi = (a == 0) ? g_w0h : (a == 1 ? g_w1h : g_w2h);
    uint16_t* lo = (a == 0) ? g_w0l : (a == 1 ? g_w1l : g_w2l);
    const size_t n = (a == 0) ? (size_t)G3_ * K0_ : (size_t)G3_ * H_;
    size_t stride = (size_t)gridDim.x * blockDim.x * 4;
    for (size_t i = ((size_t)blockIdx.x * blockDim.x + threadIdx.x) * 4; i < n; i += stride) {
        float4 v = *(const float4*)(src + i);
        __nv_bfloat16 h0 = __float2bfloat16(v.x), h1 = __float2bfloat16(v.y);
        __nv_bfloat16 h2 = __float2bfloat16(v.z), h3 = __float2bfloat16(v.w);
        __nv_bfloat16* hp = (__nv_bfloat16*)(hi + i);
        __nv_bfloat16* lp = (__nv_bfloat16*)(lo + i);
        hp[0] = h0; hp[1] = h1; hp[2] = h2; hp[3] = h3;
        lp[0] = __float2bfloat16(v.x - __bfloat162float(h0));
        lp[1] = __float2bfloat16(v.y - __bfloat162float(h1));
        lp[2] = __float2bfloat16(v.z - __bfloat162float(h2));
        lp[3] = __float2bfloat16(v.w - __bfloat162float(h3));
    }
}

// ---------------- WMMA bf16-split projection GEMM ----------------
__global__ __launch_bounds__(256, 1)
void proj_wmma_kernel(int K, int asel, int wsel)
{
    extern __shared__ __nv_bfloat16 smem[];
    const uint32_t sbase = smem_u32(smem);
    const int tid = threadIdx.x;
    const int wid = tid >> 5;
    const int m0 = blockIdx.x * 128;
    const int n0 = blockIdx.y * 128;

    const uint16_t* Ah = asel ? g_seqh : g_xh;
    const uint16_t* Al = asel ? g_seql : g_xl;
    const uint16_t* Bh = (wsel == 0) ? g_w0h : (wsel == 1 ? g_w1h : g_w2h);
    const uint16_t* Bl = (wsel == 0) ? g_w0l : (wsel == 1 ? g_w1l : g_w2l);

    // zero hidden-state buffers for the recurrence that follows this launch
    if (blockIdx.x == 0 && blockIdx.y == 0) {
        float4 z = make_float4(0.f, 0.f, 0.f, 0.f);
        float4* hp = reinterpret_cast<float4*>(&g_h[0][0]);
        for (int i = tid; i < 2 * B_ * H_ / 4; i += 256) hp[i] = z;
    }

    const uint16_t* srcs[4] = {Ah + (size_t)m0 * K, Al + (size_t)m0 * K,
                               Bh + (size_t)n0 * K, Bl + (size_t)n0 * K};

    const int nC = K >> 6;

    {
#pragma unroll
        for (int i = 0; i < 16; ++i) {
            int idx  = tid + (i << 8);
            int tile = idx >> 10;
            int rem  = idx & 1023;
            int row  = rem >> 3;
            int c    = rem & 7;
            uint32_t dst = sbase + tile * (TILE_ELEM * 2) + row * (TPITCH * 2) + c * 16;
            cp_async16(dst, srcs[tile] + (size_t)row * K + c * 8);
        }
        cp_commit();
    }

    wmma::fragment<wmma::accumulator, 16, 16, 16, float> acc[2][4];
#pragma unroll
    for (int m = 0; m < 2; ++m)
#pragma unroll
        for (int n = 0; n < 4; ++n) wmma::fill_fragment(acc[m][n], 0.0f);

    const int wm = wid & 3;
    const int wn = wid >> 2;

    for (int c = 0; c < nC; ++c) {
        const int buf = c & 1;
        if (c + 1 < nC) {
            const int k0 = (c + 1) << 6;
            const uint32_t bb = sbase + ((buf ^ 1) ? BUF_ELEM * 2 : 0);
#pragma unroll
            for (int i = 0; i < 16; ++i) {
                int idx  = tid + (i << 8);
                int tile = idx >> 10;
                int rem  = idx & 1023;
                int row  = rem >> 3;
                int cc   = rem & 7;
                uint32_t dst = bb + tile * (TILE_ELEM * 2) + row * (TPITCH * 2) + cc * 16;
                cp_async16(dst, srcs[tile] + (size_t)row * K + k0 + cc * 8);
            }
            cp_commit();
            cp_wait<1>();
        } else {
            cp_wait<0>();
        }
        __syncthreads();

        const __nv_bfloat16* bufp = smem + buf * BUF_ELEM;
        const __nv_bfloat16* sAh = bufp;
        const __nv_bfloat16* sAl = bufp + TILE_ELEM;
        const __nv_bfloat16* sBh = bufp + 2 * TILE_ELEM;
        const __nv_bfloat16* sBl = bufp + 3 * TILE_ELEM;

#pragma unroll
        for (int ks = 0; ks < 4; ++ks) {
            wmma::fragment<wmma::matrix_a, 16, 16, 16, __nv_bfloat16, wmma::row_major> ah[2], al[2];
#pragma unroll
            for (int m = 0; m < 2; ++m) {
                wmma::load_matrix_sync(ah[m], sAh + (wm * 32 + m * 16) * TPITCH + ks * 16, TPITCH);
                wmma::load_matrix_sync(al[m], sAl + (wm * 32 + m * 16) * TPITCH + ks * 16, TPITCH);
            }
#pragma unroll
            for (int n = 0; n < 4; ++n) {
                wmma::fragment<wmma::matrix_b, 16, 16, 16, __nv_bfloat16, wmma::col_major> bh, bl;
                wmma::load_matrix_sync(bh, sBh + (wn * 64 + n * 16) * TPITCH + ks * 16, TPITCH);
#pragma unroll
                for (int m = 0; m < 2; ++m) {
                    wmma::mma_sync(acc[m][n], ah[m], bh, acc[m][n]);
                    wmma::mma_sync(acc[m][n], al[m], bh, acc[m][n]);
                }
                wmma::load_matrix_sync(bl, sBl + (wn * 64 + n * 16) * TPITCH + ks * 16, TPITCH);
#pragma unroll
                for (int m = 0; m < 2; ++m)
                    wmma::mma_sync(acc[m][n], ah[m], bl, acc[m][n]);
            }
        }
        __syncthreads();
    }

#pragma unroll
    for (int m = 0; m < 2; ++m)
#pragma unroll
        for (int n = 0; n < 4; ++n) {
            float* dst = g_xg_mn + (size_t)(m0 + wm * 32 + m * 16) * G3_
                                 + n0 + wn * 64 + n * 16;
            wmma::store_matrix_sync(dst, acc[m][n], G3_, wmma::mem_row_major);
        }
}

// ---------------- transpose [m][n] -> [t][gate][b], add bias ----------------
__global__ __launch_bounds__(256)
void xg_trans_kernel(const float* __restrict__ bias) {
    __shared__ float sm[64][33];
    const int t   = blockIdx.x;
    const int g0  = blockIdx.y * 32;
    const int tid = threadIdx.x;
    const int gg  = tid & 31;
    const int br  = tid >> 5;
    const float bv = bias[g0 + gg];
#pragma unroll
    for (int i = 0; i < 8; ++i) {
        int b = br + i * 8;
        sm[b][gg] = g_xg_mn[((size_t)b * T_ + t) * G3_ + g0 + gg] + bv;
    }
    __syncthreads();
    const int b  = tid & 63;
    const int gi = tid >> 6;
#pragma unroll
    for (int i = 0; i < 8; ++i) {
        int g = gi + i * 4;
        g_xg[((size_t)t * G3_ + g0 + g) * B_ + b] = sm[b][g];
    }
}

// ---------------- persistent GRU recurrence (batch-group decomposition) ----------------
// CTA c = (bg, ug): owns batches [bg*4, bg*4+4) x units [ug*32, ug*32+32).
// Per step it reads h only for its 4 batches (4 KB), barriers only with the
// 7 other CTAs of its batch group. Batch groups drift independently.
__global__ __launch_bounds__(RT_, 1)
void gru_recur_kernel(const float* __restrict__ w_hh,
                      const float* __restrict__ b_hh,
                      int layer)
{
    extern __shared__ float smf[];
    float* ws  = smf;                        // [96][WPITCH]
    float* hs  = ws + 3 * UC_ * WPITCH;      // [4][WPITCH]
    float* red = hs + BC_ * WPITCH;          // [128][3]

    const int t   = threadIdx.x;
    const int p   = t & 127;
    const int kh  = t >> 7;                  // k half
    const int b   = p & 3;                   // local batch
    const int u   = p >> 2;                  // local unit
    const int cta = blockIdx.x;
    const int bg  = cta >> 3;
    const int ug  = cta & 7;
    const int b0  = bg * BC_;
    const int u0  = ug * UC_;
    const int j   = u0 + u;                  // global unit

    // load this CTA's 96 w_hh rows (3 gates x 32 units), 256 floats each
    for (int q = t; q < 96 * 64; q += RT_) {
        int row = q >> 6;                    // 0..95
        int c4  = (q & 63) << 2;
        int g   = row >> 5;
        int uu  = row & 31;
        *(float4*)&ws[row * WPITCH + c4] =
            *(const float4*)&w_hh[((size_t)(g * H_ + u0 + uu)) * H_ + c4];
    }

    const float bhr = b_hh[j];
    const float bhz = b_hh[H_ + j];
    const float bhn = b_hh[2 * H_ + j];
    const float* wr = &ws[(0 * UC_ + u) * WPITCH];
    const float* wz = &ws[(1 * UC_ + u) * WPITCH];
    const float* wn = &ws[(2 * UC_ + u) * WPITCH];
    __nv_bfloat16* outh = (__nv_bfloat16*)g_seqh;
    __nv_bfloat16* outl = (__nv_bfloat16*)g_seql;
    int* barp = &g_bar2[(layer * GB_ + bg) * T_];
    __syncthreads();

    for (int step = 0; step < T_; ++step) {
        const float* hcur = g_h[step & 1];
        float*       hnxt = g_h[(step & 1) ^ 1];

        // prefetch xg (precomputed, independent of barrier)
        float xr = 0.f, xz = 0.f, xn = 0.f;
        if (!kh) {
            const float* xgp = g_xg + (size_t)step * G3_ * B_;
            xr = __ldg(&xgp[(0 * H_ + j) * B_ + b0 + b]);
            xz = __ldg(&xgp[(1 * H_ + j) * B_ + b0 + b]);
            xn = __ldg(&xgp[(2 * H_ + j) * B_ + b0 + b]);
        }

        // stage h for our 4 batches: 256 float4, one per thread
        {
            int rowb = t >> 6;
            int c4   = (t & 63) << 2;
            float4 v = __ldcg((const float4*)&hcur[(b0 + rowb) * H_ + c4]);
            *(float4*)&hs[rowb * WPITCH + c4] = v;
        }
        __syncthreads();

        // 3 half-dots (len 128) for this thread's (b, u)
        float ar = 0.f, az = 0.f, an = 0.f;
        const float* hb = &hs[b * WPITCH];
        const int k0 = kh * (H_ / 2);
#pragma unroll 8
        for (int k = k0; k < k0 + H_ / 2; k += 4) {
            float4 h4 = *(const float4*)&hb[k];
            float4 r4 = *(const float4*)&wr[k];
            float4 z4 = *(const float4*)&wz[k];
            float4 n4 = *(const float4*)&wn[k];
            ar = fmaf(h4.x, r4.x, ar); ar = fmaf(h4.y, r4.y, ar);
            ar = fmaf(h4.z, r4.z, ar); ar = fmaf(h4.w, r4.w, ar);
            az = fmaf(h4.x, z4.x, az); az = fmaf(h4.y, z4.y, az);
            az = fmaf(h4.z, z4.z, az); az = fmaf(h4.w, z4.w, az);
            an = fmaf(h4.x, n4.x, an); an = fmaf(h4.y, n4.y, an);
            an = fmaf(h4.z, n4.z, an); an = fmaf(h4.w, n4.w, an);
        }
        if (kh) {
            red[p * 3 + 0] = ar;
            red[p * 3 + 1] = az;
            red[p * 3 + 2] = an;
        }
        __syncthreads();

        float hnew = 0.f;
        if (!kh) {
            ar += red[p * 3 + 0];
            az += red[p * 3 + 1];
            an += red[p * 3 + 2];
            float r = 1.0f / (1.0f + __expf(-(xr + ar + bhr)));
            float z = 1.0f / (1.0f + __expf(-(xz + az + bhz)));
            float n = tanhf(xn + r * (an + bhn));
            float hold = hs[b * WPITCH + j];
            hnew = (1.0f - z) * n + z * hold;
            __stcg(&hnxt[(b0 + b) * H_ + j], hnew);
        }

        if (step + 1 < T_) {
            // release: own h store visible, then arrive on group counter
            __threadfence();
            __syncthreads();
            int arrived = GU_;
            if (t == 0) arrived = atomicAdd(&barp[step], 1) + 1;

            // overlap: write seq outputs while peers arrive
            if (!kh) {
                __nv_bfloat16 hh = __float2bfloat16(hnew);
                __nv_bfloat16 hl = __float2bfloat16(hnew - __bfloat162float(hh));
                size_t o = ((size_t)(b0 + b) * T_ + step) * H_ + j;
                outh[o] = hh;
                outl[o] = hl;
            }

            if (t == 0 && arrived < GU_) {
                volatile int* rp = &barp[step];
                while (*rp < GU_) { }
            }
            __syncthreads();
        } else {
            if (!kh) {
                __nv_bfloat16 hh = __float2bfloat16(hnew);
                __nv_bfloat16 hl = __float2bfloat16(hnew - __bfloat162float(hh));
                size_t o = ((size_t)(b0 + b) * T_ + step) * H_ + j;
                outh[o] = hh;
                outl[o] = hl;
            }
        }
    }
}

// ---------------- MLP head ----------------
__global__ void head_kernel(const float* __restrict__ fc1_w,
                            const float* __restrict__ fc1_b,
                            const float* __restrict__ fco_w,
                            const float* __restrict__ fco_b,
                            float* __restrict__ outp)
{
    const int b = blockIdx.x;
    const int f = threadIdx.x;
    const float* last = &g_h[0][b * H_];
    float acc = fc1_b[f];
#pragma unroll 4
    for (int k = 0; k < H_; k += 4) {
        float4 l4 = *(const float4*)&last[k];
        float4 w4 = *(const float4*)&fc1_w[(size_t)f * H_ + k];
        acc = fmaf(l4.x, w4.x, acc); acc = fmaf(l4.y, w4.y, acc);
        acc = fmaf(l4.z, w4.z, acc); acc = fmaf(l4.w, w4.w, acc);
    }
    float zz = fmaxf(acc, 0.0f) * fco_w[f];
#pragma unroll
    for (int o = 16; o > 0; o >>= 1)
        zz += __shfl_down_sync(0xffffffffu, zz, o);
    __shared__ float red4[4];
    if ((f & 31) == 0) red4[f >> 5] = zz;
    __syncthreads();
    if (f == 0) outp[b] = red4[0] + red4[1] + red4[2] + red4[3] + fco_b[0];
}

// ---------------- launch ----------------
extern "C" void kernel_launch(void* const* d_in, const int* in_sizes, int n_in,
                              void* d_out, int out_size) {
    (void)in_sizes; (void)n_in; (void)out_size;
    const float* x      = (const float*)d_in[0];
    const float* wih[3] = {(const float*)d_in[1], (const float*)d_in[5], (const float*)d_in[9]};
    const float* whh[3] = {(const float*)d_in[2], (const float*)d_in[6], (const float*)d_in[10]};
    const float* bih[3] = {(const float*)d_in[3], (const float*)d_in[7], (const float*)d_in[11]};
    const float* bhh[3] = {(const float*)d_in[4], (const float*)d_in[8], (const float*)d_in[12]};
    const float* fc1_w  = (const float*)d_in[13];
    const float* fc1_b  = (const float*)d_in[14];
    const float* fco_w  = (const float*)d_in[15];
    const float* fco_b  = (const float*)d_in[16];
    float* outp = (float*)d_out;

    cudaFuncSetAttribute(proj_wmma_kernel,
                         cudaFuncAttributeMaxDynamicSharedMemorySize, PSMEM);
    cudaFuncSetAttribute(gru_recur_kernel,
                         cudaFuncAttributeMaxDynamicSharedMemorySize, RSMEM);

    zero_bar_kernel<<<96, 256>>>();                                 // 1
    split_x_kernel<<<2048, 256>>>(x);                               // 2
    split_w_kernel<<<dim3(256, 3), 256>>>(wih[0], wih[1], wih[2]);  // 3

    dim3 pgrid(M_ / 128, G3_ / 128);
    dim3 tgrid(T_, G3_ / 32);
    const int Ks[3]   = {K0_, H_, H_};
    const int asel[3] = {0, 1, 1};

    for (int l = 0; l < 3; ++l) {
        proj_wmma_kernel<<<pgrid, 256, PSMEM>>>(Ks[l], asel[l], l);   // 4
        xg_trans_kernel<<<tgrid, 256>>>(bih[l]);                      // 5
        gru_recur_kernel<<<GB_ * GU_, RT_, RSMEM>>>(whh[l], bhh[l], l); // 6 <- ncu target
    }
    head_kernel<<<B_, 128>>>(fc1_w, fc1_b, fco_w, fco_b, outp);
}